// round 16
// baseline (speedup 1.0000x reference)
#include <cuda_runtime.h>
#include <math.h>

// Problem constants
#define NB    256   // batch
#define ND    256   // dim
#define HQ    12
#define WQ    26
#define NSP   312   // H*W query positions
#define NJ    18    // 3*6 kv positions
#define NHEAD 16
#define DHEAD 16
#define TI    16    // i-tile size
#define NTIL  20    // ceil(312/16)
#define KROW  20    // padded row stride for k/v/kv smem
#define BROW  292   // bias buffer il-stride
#define NTHR  288   // 16*18 points per tile
#define W2S   72    // w2t row stride (k-major, padded)
#define W3S   24    // w3p row stride (m-major; 24qd+g is bank-conflict-free)

__device__ __forceinline__ unsigned tf32u(float x) {
    unsigned r; asm("cvt.rna.tf32.f32 %0, %1;" : "=r"(r) : "f"(x)); return r;
}

struct __align__(16) SM {
    float qsh[256];        // q row
    float ksh[256 * KROW]; // k, [c][j]
    float vsh[256 * KROW]; // v, [c][j]
    float buf[5120];       // phase2: kv[c][KROW]; phase3: bias/attn [il][h][j] stride BROW
    float w1b[256];        // packed layer-1: [k] -> {w1x, w1y, b1, 0}
    float w2t[64 * W2S];   // cpb_w2 transposed [k][permcol(m)], tf32-pre-rounded
    float b2[64];
    float w3p[64 * W3S];   // cpb_w3 transposed [m][t], tf32-pre-rounded, padded
    float b3[16];
    float u01[580];        // per-tile per-point {u0,u1}
    float cw[312];         // conv1d_w
    float gk0[20], gk1[20], sxs[20], sys[20];
    float Ash[288];        // A[h][j]
    float pp[256];         // pooled_pre
    float red[288];        // reductions
    float stats[4];
};

__global__ void __launch_bounds__(NTHR, 2)
sca_kernel(const float* __restrict__ x, const float* __restrict__ q,
           const float* __restrict__ w_off_dw, const float* __restrict__ b_off_dw,
           const float* __restrict__ w_off_pw,
           const float* __restrict__ wk, const float* __restrict__ wv,
           const float* __restrict__ w_out, const float* __restrict__ b_out,
           const float* __restrict__ cpb_w1, const float* __restrict__ cpb_b1,
           const float* __restrict__ cpb_w2, const float* __restrict__ cpb_b2,
           const float* __restrict__ cpb_w3, const float* __restrict__ cpb_b3,
           const float* __restrict__ conv1d_w, const float* __restrict__ conv1d_b,
           const float* __restrict__ ln_g, const float* __restrict__ ln_b,
           float* __restrict__ out)
{
    extern __shared__ char smem_raw[];
    SM* sm = reinterpret_cast<SM*>(smem_raw);
    const int tid  = threadIdx.x;
    const int b    = blockIdx.x;
    const int lane = tid & 31;
    const int wid  = tid >> 5;

    // ---- load q + CPB weights + conv1d_w into smem ----
    if (tid < 256) sm->qsh[tid] = q[b * ND + tid];
    for (int idx = tid; idx < 4096; idx += NTHR) {
        int m = idx >> 6, k = idx & 63;
        // column permutation within each 8-group: p = 2*(m&3) + ((m>>2)&1).
        // Makes gemm-1 C-fragments land exactly in gemm-2 A-fragment layout.
        int pm = (m & ~7) | (2 * (m & 3)) | ((m >> 2) & 1);
        sm->w2t[k * W2S + pm] = __uint_as_float(tf32u(cpb_w2[idx]));
    }
    for (int idx = tid; idx < 1024; idx += NTHR) {
        int t = idx >> 6, m = idx & 63;
        sm->w3p[m * W3S + t] = __uint_as_float(tf32u(cpb_w3[idx]));
    }
    if (tid < 64) {
        sm->w1b[tid * 4 + 0] = cpb_w1[tid * 2];
        sm->w1b[tid * 4 + 1] = cpb_w1[tid * 2 + 1];
        sm->w1b[tid * 4 + 2] = cpb_b1[tid];
        sm->w1b[tid * 4 + 3] = 0.f;
        sm->b2[tid] = cpb_b2[tid];
    }
    if (tid < 16) sm->b3[tid] = cpb_b3[tid];
    for (int idx = tid; idx < NSP; idx += NTHR) sm->cw[idx] = conv1d_w[idx];
    __syncthreads();

    // ================= Phase 1: offsets =================
    if (tid < 256) {
        const int c = tid;
        float wdw[36];
        #pragma unroll
        for (int t = 0; t < 36; t++) wdw[t] = __ldg(w_off_dw + c * 36 + t);
        const float bdw = __ldg(b_off_dw + c);
        const float pw0 = __ldg(w_off_pw + c);
        const float pw1 = __ldg(w_off_pw + 256 + c);
        const int cbase = (c * 56) & 255;

        float p0[18], p1[18];
        #pragma unroll
        for (int oh = 0; oh < 3; oh++) {
            #pragma unroll
            for (int ow = 0; ow < 6; ow++) {
                float acc = bdw;
                #pragma unroll
                for (int kh = 0; kh < 6; kh++) {
                    int ih = oh * 4 - 1 + kh;
                    if (ih < 0 || ih >= HQ) continue;
                    #pragma unroll
                    for (int kw = 0; kw < 6; kw++) {
                        int iw = ow * 4 - 1 + kw;
                        if (iw < 0 || iw >= WQ) continue;
                        int s = ih * WQ + iw;
                        acc = fmaf(wdw[kh * 6 + kw], sm->qsh[(cbase + s) & 255], acc);
                    }
                }
                float g = 0.5f * acc * (1.0f + erff(acc * 0.70710678118654752f));
                p0[oh * 6 + ow] = pw0 * g;
                p1[oh * 6 + ow] = pw1 * g;
            }
        }
        #pragma unroll
        for (int t = 0; t < 18; t++) {
            #pragma unroll
            for (int o = 16; o > 0; o >>= 1) {
                p0[t] += __shfl_xor_sync(0xffffffffu, p0[t], o);
                p1[t] += __shfl_xor_sync(0xffffffffu, p1[t], o);
            }
        }
        if (lane == 0) {
            #pragma unroll
            for (int t = 0; t < 18; t++) {
                sm->red[wid * 36 + t]      = p0[t];
                sm->red[wid * 36 + 18 + t] = p1[t];
            }
        }
    }
    __syncthreads();
    if (tid < 36) {
        float a = 0.f;
        #pragma unroll
        for (int w8 = 0; w8 < 8; w8++) a += sm->red[w8 * 36 + tid];
        float off = tanhf(a) * 4.0f;
        if (tid < 18) {            // channel 0 -> x (grid col index)
            int j = tid;
            float vg0 = (float)(j % 6) + off;
            float n0  = 2.0f * vg0 / 2.0f - 1.0f;
            sm->gk0[j] = n0;
            sm->sxs[j] = ((n0 + 1.0f) * 26.0f - 1.0f) * 0.5f;
        } else {                   // channel 1 -> y (grid row index)
            int j = tid - 18;
            float vg1 = (float)(j / 6) + off;
            float n1  = 2.0f * vg1 / 5.0f - 1.0f;
            sm->gk1[j] = n1;
            sm->sys[j] = ((n1 + 1.0f) * 12.0f - 1.0f) * 0.5f;
        }
    }
    __syncthreads();

    // ================= Phase 2: grid-sample + k/v =================
    if (tid < 256) {
        const int c = tid;
        float* kvsh = sm->buf;                 // [c][KROW]
        const float* xrow = x + ((size_t)b * ND + c) * NSP;
        #pragma unroll
        for (int j = 0; j < NJ; j++) {
            float xs = sm->sxs[j], ys = sm->sys[j];
            float x0f = floorf(xs), y0f = floorf(ys);
            int x0 = (int)x0f, y0 = (int)y0f;
            float wx1 = xs - x0f, wx0 = 1.0f - wx1;
            float wy1 = ys - y0f, wy0 = 1.0f - wy1;
            int x1 = x0 + 1, y1 = y0 + 1;
            bool vx0 = (x0 >= 0) & (x0 < WQ), vx1 = (x1 >= 0) & (x1 < WQ);
            bool vy0 = (y0 >= 0) & (y0 < HQ), vy1 = (y1 >= 0) & (y1 < HQ);
            float v00 = (vx0 & vy0) ? __ldg(xrow + y0 * WQ + x0) : 0.f;
            float v01 = (vx1 & vy0) ? __ldg(xrow + y0 * WQ + x1) : 0.f;
            float v10 = (vx0 & vy1) ? __ldg(xrow + y1 * WQ + x0) : 0.f;
            float v11 = (vx1 & vy1) ? __ldg(xrow + y1 * WQ + x1) : 0.f;
            kvsh[c * KROW + j] = (v00 * wx0 + v01 * wx1) * wy0 + (v10 * wx0 + v11 * wx1) * wy1;
        }
    }
    __syncthreads();
    if (tid < 256) {   // k/v GEMM: thread = output channel
        const int o = tid;
        float ak[18], av[18];
        #pragma unroll
        for (int j = 0; j < NJ; j++) { ak[j] = 0.f; av[j] = 0.f; }
        const float* wkr = wk + o * ND;
        const float* wvr = wv + o * ND;
        const float* kvsh = sm->buf;
        for (int c4 = 0; c4 < ND; c4 += 4) {
            float4 a = *(const float4*)(wkr + c4);
            float4 v = *(const float4*)(wvr + c4);
            const float wkx[4] = {a.x, a.y, a.z, a.w};
            const float wvx[4] = {v.x, v.y, v.z, v.w};
            #pragma unroll
            for (int u = 0; u < 4; u++) {
                const float* kvr = kvsh + (c4 + u) * KROW;
                float wk1 = wkx[u], wv1 = wvx[u];
                #pragma unroll
                for (int j = 0; j < NJ; j++) {
                    float kvv = kvr[j];
                    ak[j] = fmaf(wk1, kvv, ak[j]);
                    av[j] = fmaf(wv1, kvv, av[j]);
                }
            }
        }
        #pragma unroll
        for (int j = 0; j < NJ; j++) {
            sm->ksh[o * KROW + j] = ak[j];
            sm->vsh[o * KROW + j] = av[j];
        }
    }
    __syncthreads();

    // ================= Phase 3: CPB MLP (2x tensor-core gemm) + attention =================
    float A_reg = 0.f;                 // one (h,j) pair per thread
    const int hA = tid / 18, jA = tid % 18;
    const int ilM = tid / 18, jM = tid % 18;   // point index p = tid
    const int g = lane >> 2;           // mma group id (row)
    const int qd = lane & 3;           // mma thread-in-group (col)

    for (int tile = 0; tile < NTIL; tile++) {
        const int i0 = tile * TI;
        // ---- (a0) per-point u0/u1 into smem ----
        {
            const int i = i0 + ilM;
            float u0 = 0.f, u1 = 0.f;
            if (i < NSP) {
                int wq_i = i % WQ, hq_i = i / WQ;
                float gq0 = 2.0f * (float)wq_i / 11.0f - 1.0f;
                float gq1 = 2.0f * (float)hq_i / 25.0f - 1.0f;
                float px = gq0 - sm->gk0[jM];
                float py = gq1 - sm->gk1[jM];
                u0 = copysignf(log1pf(fabsf(px)), px);
                u1 = copysignf(log1pf(fabsf(py)), py);
            }
            sm->u01[tid * 2]     = u0;
            sm->u01[tid * 2 + 1] = u1;
        }
        __syncthreads();
        // ---- (a1) MLP: gemm-1 (layer-2) then gemm-2 (layer-3), both m16n8k8.tf32 ----
        #pragma unroll 1
        for (int sub = 0; sub < 2; sub++) {
            const int mt = wid * 2 + sub;          // 0..17
            const int pr0 = mt * 16 + g;           // point rows owned by this lane
            const int pr1 = pr0 + 8;
            float2 uA = ((const float2*)sm->u01)[pr0];
            float2 uB = ((const float2*)sm->u01)[pr1];
            float c[8][4];
            #pragma unroll
            for (int nt = 0; nt < 8; nt++) {
                c[nt][0] = 0.f; c[nt][1] = 0.f; c[nt][2] = 0.f; c[nt][3] = 0.f;
            }
            const unsigned* w2u = (const unsigned*)sm->w2t;
            #pragma unroll
            for (int ks = 0; ks < 8; ks++) {
                int k0 = ks * 8 + qd;
                float4 wk0 = ((const float4*)sm->w1b)[k0];
                float4 wk1 = ((const float4*)sm->w1b)[k0 + 4];
                float h00 = fmaxf(fmaf(wk0.x, uA.x, fmaf(wk0.y, uA.y, wk0.z)), 0.f);
                float h10 = fmaxf(fmaf(wk0.x, uB.x, fmaf(wk0.y, uB.y, wk0.z)), 0.f);
                float h01 = fmaxf(fmaf(wk1.x, uA.x, fmaf(wk1.y, uA.y, wk1.z)), 0.f);
                float h11 = fmaxf(fmaf(wk1.x, uB.x, fmaf(wk1.y, uB.y, wk1.z)), 0.f);
                unsigned a0 = tf32u(h00), a1 = tf32u(h10), a2 = tf32u(h01), a3 = tf32u(h11);
                int rowA = k0 * W2S;
                int rowB = rowA + 4 * W2S;
                #pragma unroll
                for (int nt = 0; nt < 8; nt++) {
                    unsigned b0 = w2u[rowA + nt * 8 + g];
                    unsigned b1 = w2u[rowB + nt * 8 + g];
                    asm volatile(
                        "mma.sync.aligned.m16n8k8.row.col.f32.tf32.tf32.f32 "
                        "{%0,%1,%2,%3},{%4,%5,%6,%7},{%8,%9},{%0,%1,%2,%3};"
                        : "+f"(c[nt][0]), "+f"(c[nt][1]), "+f"(c[nt][2]), "+f"(c[nt][3])
                        : "r"(a0), "r"(a1), "r"(a2), "r"(a3), "r"(b0), "r"(b1));
                }
            }
            // ---- gemm-2: bias = relu(c + b2) @ w3.  Thanks to the w2t column
            // permutation, c[nt] holds actual m-cols {nt*8+qd, nt*8+qd+4} for rows
            // {g, g+8} — exactly the A-fragment of m16n8k8 for k-chunk nt.
            float c2a[4] = {0.f, 0.f, 0.f, 0.f};   // n-tile 0: t = 0..7
            float c2b[4] = {0.f, 0.f, 0.f, 0.f};   // n-tile 1: t = 8..15
            const unsigned* w3u = (const unsigned*)sm->w3p;
            #pragma unroll
            for (int nt = 0; nt < 8; nt++) {
                int mlo = nt * 8 + qd;            // actual m of c[nt][0], c[nt][2]
                int mhi = mlo + 4;                // actual m of c[nt][1], c[nt][3]
                float b2a = sm->b2[mlo], b2b = sm->b2[mhi];
                unsigned a0 = tf32u(fmaxf(c[nt][0] + b2a, 0.f));  // (row g,   k=mlo)
                unsigned a1 = tf32u(fmaxf(c[nt][2] + b2a, 0.f));  // (row g+8, k=mlo)
                unsigned a2 = tf32u(fmaxf(c[nt][1] + b2b, 0.f));  // (row g,   k=mhi)
                unsigned a3 = tf32u(fmaxf(c[nt][3] + b2b, 0.f));  // (row g+8, k=mhi)
                unsigned b0 = w3u[mlo * W3S + g];
                unsigned b1 = w3u[mhi * W3S + g];
                asm volatile(
                    "mma.sync.aligned.m16n8k8.row.col.f32.tf32.tf32.f32 "
                    "{%0,%1,%2,%3},{%4,%5,%6,%7},{%8,%9},{%0,%1,%2,%3};"
                    : "+f"(c2a[0]), "+f"(c2a[1]), "+f"(c2a[2]), "+f"(c2a[3])
                    : "r"(a0), "r"(a1), "r"(a2), "r"(a3), "r"(b0), "r"(b1));
                unsigned b2_ = w3u[mlo * W3S + 8 + g];
                unsigned b3_ = w3u[mhi * W3S + 8 + g];
                asm volatile(
                    "mma.sync.aligned.m16n8k8.row.col.f32.tf32.tf32.f32 "
                    "{%0,%1,%2,%3},{%4,%5,%6,%7},{%8,%9},{%0,%1,%2,%3};"
                    : "+f"(c2b[0]), "+f"(c2b[1]), "+f"(c2b[2]), "+f"(c2b[3])
                    : "r"(a0), "r"(a1), "r"(a2), "r"(a3), "r"(b2_), "r"(b3_));
            }
            // write bias: rows pr0/pr1, t-cols {2qd, 2qd+1} and {8+2qd, 8+2qd+1}
            {
                int il0 = pr0 / 18, j0 = pr0 % 18;
                int il1 = pr1 / 18, j1 = pr1 % 18;
                float* d0 = sm->buf + il0 * BROW + j0;
                float* d1 = sm->buf + il1 * BROW + j1;
                int t0 = 2 * qd, t1 = 2 * qd + 1;
                d0[t0 * 18]       = c2a[0] + sm->b3[t0];
                d0[t1 * 18]       = c2a[1] + sm->b3[t1];
                d1[t0 * 18]       = c2a[2] + sm->b3[t0];
                d1[t1 * 18]       = c2a[3] + sm->b3[t1];
                d0[(8 + t0) * 18] = c2b[0] + sm->b3[8 + t0];
                d0[(8 + t1) * 18] = c2b[1] + sm->b3[8 + t1];
                d1[(8 + t0) * 18] = c2b[2] + sm->b3[8 + t0];
                d1[(8 + t1) * 18] = c2b[3] + sm->b3[8 + t1];
            }
        }
        __syncthreads();
        // ---- (c) qk + bias + softmax + conv1d weighting ----
        if (tid < 256) {
            const int h = tid >> 4, il = tid & 15;
            const int i = i0 + il;
            float* brow = sm->buf + il * BROW + h * 18;
            if (i < NSP) {
                float srow[18];
                #pragma unroll
                for (int j = 0; j < NJ; j++) srow[j] = brow[j];
                #pragma unroll
                for (int d = 0; d < DHEAD; d++) {
                    int c = h * 16 + d;
                    float qv = 0.25f * sm->qsh[(c * 56 + i) & 255];
                    const float4* kr4 = (const float4*)(sm->ksh + c * KROW);
                    float4 k0 = kr4[0], k1 = kr4[1], k2 = kr4[2], k3 = kr4[3];
                    float2 k4 = *(const float2*)(sm->ksh + c * KROW + 16);
                    srow[0]  = fmaf(qv, k0.x, srow[0]);  srow[1]  = fmaf(qv, k0.y, srow[1]);
                    srow[2]  = fmaf(qv, k0.z, srow[2]);  srow[3]  = fmaf(qv, k0.w, srow[3]);
                    srow[4]  = fmaf(qv, k1.x, srow[4]);  srow[5]  = fmaf(qv, k1.y, srow[5]);
                    srow[6]  = fmaf(qv, k1.z, srow[6]);  srow[7]  = fmaf(qv, k1.w, srow[7]);
                    srow[8]  = fmaf(qv, k2.x, srow[8]);  srow[9]  = fmaf(qv, k2.y, srow[9]);
                    srow[10] = fmaf(qv, k2.z, srow[10]); srow[11] = fmaf(qv, k2.w, srow[11]);
                    srow[12] = fmaf(qv, k3.x, srow[12]); srow[13] = fmaf(qv, k3.y, srow[13]);
                    srow[14] = fmaf(qv, k3.z, srow[14]); srow[15] = fmaf(qv, k3.w, srow[15]);
                    srow[16] = fmaf(qv, k4.x, srow[16]); srow[17] = fmaf(qv, k4.y, srow[17]);
                }
                float mx = srow[0];
                #pragma unroll
                for (int j = 1; j < NJ; j++) mx = fmaxf(mx, srow[j]);
                float ssum = 0.f;
                #pragma unroll
                for (int j = 0; j < NJ; j++) { float e = __expf(srow[j] - mx); srow[j] = e; ssum += e; }
                float sc = sm->cw[i] / ssum;
                #pragma unroll
                for (int j = 0; j < NJ; j++) brow[j] = srow[j] * sc;
            } else {
                #pragma unroll
                for (int j = 0; j < NJ; j++) brow[j] = 0.f;
            }
        }
        __syncthreads();
        // ---- (e) reduce over il into A: one (h,j) pair per thread ----
        {
            const float* src = sm->buf + hA * 18 + jA;
            float a = 0.f;
            #pragma unroll
            for (int il = 0; il < TI; il++) a += src[il * BROW];
            A_reg += a;
        }
        __syncthreads();
    }
    sm->Ash[hA * NJ + jA] = A_reg;
    __syncthreads();

    // ================= Tail: pooled attention output -> w_out -> residual -> LN =================
    if (tid < 256) {
        const int h = tid >> 4;
        const float* vr = sm->vsh + tid * KROW;
        const float* Ar = sm->Ash + h * NJ;
        float acc = 0.f;
        #pragma unroll
        for (int j = 0; j < NJ; j++) acc = fmaf(Ar[j], vr[j], acc);
        sm->pp[tid] = acc;
    }
    __syncthreads();
    {
        float y = 0.f;
        if (tid < 256) {
            float s0 = 0.f, s1 = 0.f, s2 = 0.f, s3 = 0.f;
            for (int t = 0; t < NSP; t += 4) {
                s0 += sm->cw[t]; s1 += sm->cw[t + 1]; s2 += sm->cw[t + 2]; s3 += sm->cw[t + 3];
            }
            float sumcw = (s0 + s1) + (s2 + s3);
            float acc = sumcw * __ldg(b_out + tid) + __ldg(conv1d_b);
            const float* wor = w_out + tid * ND;
            for (int c = 0; c < ND; c += 4) {
                float4 w4 = *(const float4*)(wor + c);
                acc = fmaf(w4.x, sm->pp[c],     acc);
                acc = fmaf(w4.y, sm->pp[c + 1], acc);
                acc = fmaf(w4.z, sm->pp[c + 2], acc);
                acc = fmaf(w4.w, sm->pp[c + 3], acc);
            }
            y = acc + sm->qsh[tid];
            float s = y, sq = y * y;
            #pragma unroll
            for (int o = 16; o > 0; o >>= 1) {
                s  += __shfl_xor_sync(0xffffffffu, s,  o);
                sq += __shfl_xor_sync(0xffffffffu, sq, o);
            }
            if (lane == 0) { sm->red[wid] = s; sm->red[8 + wid] = sq; }
        }
        __syncthreads();
        if (tid == 0) {
            float t1 = 0.f, t2 = 0.f;
            #pragma unroll
            for (int w8 = 0; w8 < 8; w8++) { t1 += sm->red[w8]; t2 += sm->red[8 + w8]; }
            float mu = t1 * (1.0f / 256.0f);
            sm->stats[0] = mu;
            sm->stats[1] = t2 * (1.0f / 256.0f) - mu * mu;
        }
        __syncthreads();
        if (tid < 256) {
            float mu = sm->stats[0], var = sm->stats[1];
            out[b * ND + tid] = (y - mu) * rsqrtf(var + 1e-5f) * __ldg(ln_g + tid) + __ldg(ln_b + tid);
        }
    }
}

extern "C" void kernel_launch(void* const* d_in, const int* in_sizes, int n_in,
                              void* d_out, int out_size)
{
    const float* x        = (const float*)d_in[0];
    const float* q        = (const float*)d_in[1];
    const float* w_off_dw = (const float*)d_in[2];
    const float* b_off_dw = (const float*)d_in[3];
    const float* w_off_pw = (const float*)d_in[4];
    const float* wk       = (const float*)d_in[5];
    const float* wv       = (const float*)d_in[6];
    const float* w_out    = (const float*)d_in[7];
    const float* b_out    = (const float*)d_in[8];
    const float* cpb_w1   = (const float*)d_in[9];
    const float* cpb_b1   = (const float*)d_in[10];
    const float* cpb_w2   = (const float*)d_in[11];
    const float* cpb_b2   = (const float*)d_in[12];
    const float* cpb_w3   = (const float*)d_in[13];
    const float* cpb_b3   = (const float*)d_in[14];
    const float* conv1d_w = (const float*)d_in[15];
    const float* conv1d_b = (const float*)d_in[16];
    const float* ln_g     = (const float*)d_in[17];
    const float* ln_b     = (const float*)d_in[18];
    float* out = (float*)d_out;

    (void)in_sizes; (void)n_in; (void)out_size;

    cudaFuncSetAttribute(sca_kernel, cudaFuncAttributeMaxDynamicSharedMemorySize, (int)sizeof(SM));
    sca_kernel<<<NB, NTHR, sizeof(SM)>>>(x, q, w_off_dw, b_off_dw, w_off_pw, wk, wv,
                                         w_out, b_out, cpb_w1, cpb_b1, cpb_w2, cpb_b2,
                                         cpb_w3, cpb_b3, conv1d_w, conv1d_b, ln_g, ln_b, out);
}

// round 17
// speedup vs baseline: 1.0819x; 1.0819x over previous
#include <cuda_runtime.h>
#include <math.h>

// Problem constants
#define NB    256   // batch
#define ND    256   // dim
#define HQ    12
#define WQ    26
#define NSP   312   // H*W query positions
#define NJ    18    // 3*6 kv positions
#define NHEAD 16
#define DHEAD 16
#define TI    16    // i-tile size
#define NTIL  20    // ceil(312/16)
#define KROW  20    // padded row stride for k/v/kv smem
#define BROW  293   // bias buffer il-stride (293 mod 32 = 5: conflict-free il access)
#define NTHR  288   // 16*18 points per tile
#define W2S   72    // w2t row stride (k-major, padded)
#define W3S   20    // w3p row stride (m-major, padded)

__device__ __forceinline__ unsigned tf32u(float x) {
    unsigned r; asm("cvt.rna.tf32.f32 %0, %1;" : "=r"(r) : "f"(x)); return r;
}

struct __align__(16) SM {
    float qsh[256];        // q row
    float ksh[256 * KROW]; // k, [c][j]
    float vsh[256 * KROW]; // v, [c][j]
    float buf[5120];       // phase2: kv[c][KROW]; phase3: bias [il][h][j] stride BROW
    float w1b[256];        // packed layer-1: [k] -> {w1x, w1y, b1, 0}
    float w2t[64 * W2S];   // cpb_w2 transposed [k][m], tf32-pre-rounded
    float b2[64];
    float w3p[64 * W3S];   // cpb_w3 transposed [m][t], padded
    float b3[16];
    float u01[580];        // per-tile per-point {u0,u1}
    float cw[312];         // conv1d_w
    float gk0[20], gk1[20], sxs[20], sys[20];
    float Ash[288];        // A[h][j]
    float pp[256];         // pooled_pre
    float red[288];        // reductions
    float stats[4];
};

__global__ void __launch_bounds__(NTHR, 2)
sca_kernel(const float* __restrict__ x, const float* __restrict__ q,
           const float* __restrict__ w_off_dw, const float* __restrict__ b_off_dw,
           const float* __restrict__ w_off_pw,
           const float* __restrict__ wk, const float* __restrict__ wv,
           const float* __restrict__ w_out, const float* __restrict__ b_out,
           const float* __restrict__ cpb_w1, const float* __restrict__ cpb_b1,
           const float* __restrict__ cpb_w2, const float* __restrict__ cpb_b2,
           const float* __restrict__ cpb_w3, const float* __restrict__ cpb_b3,
           const float* __restrict__ conv1d_w, const float* __restrict__ conv1d_b,
           const float* __restrict__ ln_g, const float* __restrict__ ln_b,
           float* __restrict__ out)
{
    extern __shared__ char smem_raw[];
    SM* sm = reinterpret_cast<SM*>(smem_raw);
    const int tid  = threadIdx.x;
    const int b    = blockIdx.x;
    const int lane = tid & 31;
    const int wid  = tid >> 5;

    // ---- load q + CPB weights + conv1d_w into smem ----
    if (tid < 256) sm->qsh[tid] = q[b * ND + tid];
    for (int idx = tid; idx < 4096; idx += NTHR) {
        int m = idx >> 6, k = idx & 63;
        sm->w2t[k * W2S + m] = __uint_as_float(tf32u(cpb_w2[idx]));
    }
    for (int idx = tid; idx < 1024; idx += NTHR) {
        int t = idx >> 6, m = idx & 63;
        sm->w3p[m * W3S + t] = cpb_w3[idx];
    }
    if (tid < 64) {
        sm->w1b[tid * 4 + 0] = cpb_w1[tid * 2];
        sm->w1b[tid * 4 + 1] = cpb_w1[tid * 2 + 1];
        sm->w1b[tid * 4 + 2] = cpb_b1[tid];
        sm->w1b[tid * 4 + 3] = 0.f;
        sm->b2[tid] = cpb_b2[tid];
    }
    if (tid < 16) sm->b3[tid] = cpb_b3[tid];
    for (int idx = tid; idx < NSP; idx += NTHR) sm->cw[idx] = conv1d_w[idx];
    __syncthreads();

    // ================= Phase 1: offsets =================
    if (tid < 256) {
        const int c = tid;
        float wdw[36];
        #pragma unroll
        for (int t = 0; t < 36; t++) wdw[t] = __ldg(w_off_dw + c * 36 + t);
        const float bdw = __ldg(b_off_dw + c);
        const float pw0 = __ldg(w_off_pw + c);
        const float pw1 = __ldg(w_off_pw + 256 + c);
        const int cbase = (c * 56) & 255;

        float p0[18], p1[18];
        #pragma unroll
        for (int oh = 0; oh < 3; oh++) {
            #pragma unroll
            for (int ow = 0; ow < 6; ow++) {
                float acc = bdw;
                #pragma unroll
                for (int kh = 0; kh < 6; kh++) {
                    int ih = oh * 4 - 1 + kh;
                    if (ih < 0 || ih >= HQ) continue;
                    #pragma unroll
                    for (int kw = 0; kw < 6; kw++) {
                        int iw = ow * 4 - 1 + kw;
                        if (iw < 0 || iw >= WQ) continue;
                        int s = ih * WQ + iw;
                        acc = fmaf(wdw[kh * 6 + kw], sm->qsh[(cbase + s) & 255], acc);
                    }
                }
                float g = 0.5f * acc * (1.0f + erff(acc * 0.70710678118654752f));
                p0[oh * 6 + ow] = pw0 * g;
                p1[oh * 6 + ow] = pw1 * g;
            }
        }
        #pragma unroll
        for (int t = 0; t < 18; t++) {
            #pragma unroll
            for (int o = 16; o > 0; o >>= 1) {
                p0[t] += __shfl_xor_sync(0xffffffffu, p0[t], o);
                p1[t] += __shfl_xor_sync(0xffffffffu, p1[t], o);
            }
        }
        if (lane == 0) {
            #pragma unroll
            for (int t = 0; t < 18; t++) {
                sm->red[wid * 36 + t]      = p0[t];
                sm->red[wid * 36 + 18 + t] = p1[t];
            }
        }
    }
    __syncthreads();
    if (tid < 36) {
        float a = 0.f;
        #pragma unroll
        for (int w8 = 0; w8 < 8; w8++) a += sm->red[w8 * 36 + tid];
        float off = tanhf(a) * 4.0f;
        if (tid < 18) {            // channel 0 -> x (grid col index)
            int j = tid;
            float vg0 = (float)(j % 6) + off;
            float n0  = 2.0f * vg0 / 2.0f - 1.0f;
            sm->gk0[j] = n0;
            sm->sxs[j] = ((n0 + 1.0f) * 26.0f - 1.0f) * 0.5f;
        } else {                   // channel 1 -> y (grid row index)
            int j = tid - 18;
            float vg1 = (float)(j / 6) + off;
            float n1  = 2.0f * vg1 / 5.0f - 1.0f;
            sm->gk1[j] = n1;
            sm->sys[j] = ((n1 + 1.0f) * 12.0f - 1.0f) * 0.5f;
        }
    }
    __syncthreads();

    // ================= Phase 2: grid-sample + k/v =================
    if (tid < 256) {
        const int c = tid;
        float* kvsh = sm->buf;                 // [c][KROW]
        const float* xrow = x + ((size_t)b * ND + c) * NSP;
        #pragma unroll
        for (int j = 0; j < NJ; j++) {
            float xs = sm->sxs[j], ys = sm->sys[j];
            float x0f = floorf(xs), y0f = floorf(ys);
            int x0 = (int)x0f, y0 = (int)y0f;
            float wx1 = xs - x0f, wx0 = 1.0f - wx1;
            float wy1 = ys - y0f, wy0 = 1.0f - wy1;
            int x1 = x0 + 1, y1 = y0 + 1;
            bool vx0 = (x0 >= 0) & (x0 < WQ), vx1 = (x1 >= 0) & (x1 < WQ);
            bool vy0 = (y0 >= 0) & (y0 < HQ), vy1 = (y1 >= 0) & (y1 < HQ);
            float v00 = (vx0 & vy0) ? __ldg(xrow + y0 * WQ + x0) : 0.f;
            float v01 = (vx1 & vy0) ? __ldg(xrow + y0 * WQ + x1) : 0.f;
            float v10 = (vx0 & vy1) ? __ldg(xrow + y1 * WQ + x0) : 0.f;
            float v11 = (vx1 & vy1) ? __ldg(xrow + y1 * WQ + x1) : 0.f;
            kvsh[c * KROW + j] = (v00 * wx0 + v01 * wx1) * wy0 + (v10 * wx0 + v11 * wx1) * wy1;
        }
    }
    __syncthreads();
    if (tid < 256) {   // k/v GEMM: thread = output channel
        const int o = tid;
        float ak[18], av[18];
        #pragma unroll
        for (int j = 0; j < NJ; j++) { ak[j] = 0.f; av[j] = 0.f; }
        const float* wkr = wk + o * ND;
        const float* wvr = wv + o * ND;
        const float* kvsh = sm->buf;
        for (int c4 = 0; c4 < ND; c4 += 4) {
            float4 a = *(const float4*)(wkr + c4);
            float4 v = *(const float4*)(wvr + c4);
            const float wkx[4] = {a.x, a.y, a.z, a.w};
            const float wvx[4] = {v.x, v.y, v.z, v.w};
            #pragma unroll
            for (int u = 0; u < 4; u++) {
                const float* kvr = kvsh + (c4 + u) * KROW;
                float wk1 = wkx[u], wv1 = wvx[u];
                #pragma unroll
                for (int j = 0; j < NJ; j++) {
                    float kvv = kvr[j];
                    ak[j] = fmaf(wk1, kvv, ak[j]);
                    av[j] = fmaf(wv1, kvv, av[j]);
                }
            }
        }
        #pragma unroll
        for (int j = 0; j < NJ; j++) {
            sm->ksh[o * KROW + j] = ak[j];
            sm->vsh[o * KROW + j] = av[j];
        }
    }
    __syncthreads();

    // ================= Phase 3: CPB MLP (tensor-core) + attention =================
    float Aj[18];                      // per-(h) A accumulators (valid on (c)-warps)
    #pragma unroll
    for (int j = 0; j < NJ; j++) Aj[j] = 0.f;
    const int ilM = tid / 18, jM = tid % 18;   // point index p = tid
    const int g = lane >> 2;           // mma group id (row)
    const int qd = lane & 3;           // mma thread-in-group (col)

    for (int tile = 0; tile < NTIL; tile++) {
        const int i0 = tile * TI;
        // ---- (a0) per-point u0/u1 into smem ----
        {
            const int i = i0 + ilM;
            float u0 = 0.f, u1 = 0.f;
            if (i < NSP) {
                int wq_i = i % WQ, hq_i = i / WQ;
                float gq0 = 2.0f * (float)wq_i / 11.0f - 1.0f;
                float gq1 = 2.0f * (float)hq_i / 25.0f - 1.0f;
                float px = gq0 - sm->gk0[jM];
                float py = gq1 - sm->gk1[jM];
                u0 = copysignf(log1pf(fabsf(px)), px);
                u1 = copysignf(log1pf(fabsf(py)), py);
            }
            sm->u01[tid * 2]     = u0;
            sm->u01[tid * 2 + 1] = u1;
        }
        __syncthreads();   // u01 ready; also orders prev-tile (c) reads before a1 writes
        // ---- (a1) MLP via mma.m16n8k8.tf32: warp wid owns m-tiles {2*wid, 2*wid+1} ----
        #pragma unroll 1
        for (int sub = 0; sub < 2; sub++) {
            const int mt = wid * 2 + sub;          // 0..17
            const int pr0 = mt * 16 + g;           // point rows owned by this lane
            const int pr1 = pr0 + 8;
            float2 uA = ((const float2*)sm->u01)[pr0];
            float2 uB = ((const float2*)sm->u01)[pr1];
            float c[8][4];
            #pragma unroll
            for (int nt = 0; nt < 8; nt++) {
                c[nt][0] = 0.f; c[nt][1] = 0.f; c[nt][2] = 0.f; c[nt][3] = 0.f;
            }
            const unsigned* w2u = (const unsigned*)sm->w2t;
            #pragma unroll
            for (int ks = 0; ks < 8; ks++) {
                int k0 = ks * 8 + qd;
                float4 wk0 = ((const float4*)sm->w1b)[k0];
                float4 wk1 = ((const float4*)sm->w1b)[k0 + 4];
                float h00 = fmaxf(fmaf(wk0.x, uA.x, fmaf(wk0.y, uA.y, wk0.z)), 0.f);
                float h10 = fmaxf(fmaf(wk0.x, uB.x, fmaf(wk0.y, uB.y, wk0.z)), 0.f);
                float h01 = fmaxf(fmaf(wk1.x, uA.x, fmaf(wk1.y, uA.y, wk1.z)), 0.f);
                float h11 = fmaxf(fmaf(wk1.x, uB.x, fmaf(wk1.y, uB.y, wk1.z)), 0.f);
                unsigned a0 = tf32u(h00), a1 = tf32u(h10), a2 = tf32u(h01), a3 = tf32u(h11);
                int rowA = k0 * W2S;
                int rowB = rowA + 4 * W2S;
                #pragma unroll
                for (int nt = 0; nt < 8; nt++) {
                    unsigned b0 = w2u[rowA + nt * 8 + g];
                    unsigned b1 = w2u[rowB + nt * 8 + g];
                    asm volatile(
                        "mma.sync.aligned.m16n8k8.row.col.f32.tf32.tf32.f32 "
                        "{%0,%1,%2,%3},{%4,%5,%6,%7},{%8,%9},{%0,%1,%2,%3};"
                        : "+f"(c[nt][0]), "+f"(c[nt][1]), "+f"(c[nt][2]), "+f"(c[nt][3])
                        : "r"(a0), "r"(a1), "r"(a2), "r"(a3), "r"(b0), "r"(b1));
                }
            }
            // epilogue: relu(c + b2) folded through layer-3 into 16 t-partials per row
            float ta[16], tb[16];
            #pragma unroll
            for (int t = 0; t < 16; t++) { ta[t] = 0.f; tb[t] = 0.f; }
            #pragma unroll
            for (int nt = 0; nt < 8; nt++) {
                int m0 = nt * 8 + 2 * qd;
                float b2a = sm->b2[m0], b2b = sm->b2[m0 + 1];
                float e00 = fmaxf(c[nt][0] + b2a, 0.f);
                float e01 = fmaxf(c[nt][1] + b2b, 0.f);
                float e10 = fmaxf(c[nt][2] + b2a, 0.f);
                float e11 = fmaxf(c[nt][3] + b2b, 0.f);
                const float4* w30 = (const float4*)(sm->w3p + m0 * W3S);
                const float4* w31 = (const float4*)(sm->w3p + (m0 + 1) * W3S);
                #pragma unroll
                for (int tq = 0; tq < 4; tq++) {
                    float4 wa = w30[tq], wb = w31[tq];
                    ta[4*tq]   = fmaf(wa.x, e00, fmaf(wb.x, e01, ta[4*tq]));
                    ta[4*tq+1] = fmaf(wa.y, e00, fmaf(wb.y, e01, ta[4*tq+1]));
                    ta[4*tq+2] = fmaf(wa.z, e00, fmaf(wb.z, e01, ta[4*tq+2]));
                    ta[4*tq+3] = fmaf(wa.w, e00, fmaf(wb.w, e01, ta[4*tq+3]));
                    tb[4*tq]   = fmaf(wa.x, e10, fmaf(wb.x, e11, tb[4*tq]));
                    tb[4*tq+1] = fmaf(wa.y, e10, fmaf(wb.y, e11, tb[4*tq+1]));
                    tb[4*tq+2] = fmaf(wa.z, e10, fmaf(wb.z, e11, tb[4*tq+2]));
                    tb[4*tq+3] = fmaf(wa.w, e10, fmaf(wb.w, e11, tb[4*tq+3]));
                }
            }
            #pragma unroll
            for (int t = 0; t < 16; t++) {
                ta[t] += __shfl_xor_sync(0xffffffffu, ta[t], 1);
                ta[t] += __shfl_xor_sync(0xffffffffu, ta[t], 2);
                tb[t] += __shfl_xor_sync(0xffffffffu, tb[t], 1);
                tb[t] += __shfl_xor_sync(0xffffffffu, tb[t], 2);
            }
            if (qd == 0) {
                int il0 = pr0 / 18, j0 = pr0 % 18;
                int il1 = pr1 / 18, j1 = pr1 % 18;
                float* d0 = sm->buf + il0 * BROW + j0;
                float* d1 = sm->buf + il1 * BROW + j1;
                #pragma unroll
                for (int t = 0; t < 16; t++) {
                    d0[t * 18] = ta[t] + sm->b3[t];
                    d1[t * 18] = tb[t] + sm->b3[t];
                }
            }
        }
        __syncthreads();   // bias buffer published
        // ---- (c) qk + bias + softmax + conv1d weighting + in-warp il-reduction ----
        if (tid < 256) {
            const int h = tid >> 4, il = tid & 15;
            const int i = i0 + il;
            float srow[18];
            if (i < NSP) {
                const float* brow = sm->buf + il * BROW + h * 18;
                #pragma unroll
                for (int j = 0; j < NJ; j++) srow[j] = brow[j];
                #pragma unroll
                for (int d = 0; d < DHEAD; d++) {
                    int c = h * 16 + d;
                    float qv = 0.25f * sm->qsh[(c * 56 + i) & 255];
                    const float4* kr4 = (const float4*)(sm->ksh + c * KROW);
                    float4 k0 = kr4[0], k1 = kr4[1], k2 = kr4[2], k3 = kr4[3];
                    float2 k4 = *(const float2*)(sm->ksh + c * KROW + 16);
                    srow[0]  = fmaf(qv, k0.x, srow[0]);  srow[1]  = fmaf(qv, k0.y, srow[1]);
                    srow[2]  = fmaf(qv, k0.z, srow[2]);  srow[3]  = fmaf(qv, k0.w, srow[3]);
                    srow[4]  = fmaf(qv, k1.x, srow[4]);  srow[5]  = fmaf(qv, k1.y, srow[5]);
                    srow[6]  = fmaf(qv, k1.z, srow[6]);  srow[7]  = fmaf(qv, k1.w, srow[7]);
                    srow[8]  = fmaf(qv, k2.x, srow[8]);  srow[9]  = fmaf(qv, k2.y, srow[9]);
                    srow[10] = fmaf(qv, k2.z, srow[10]); srow[11] = fmaf(qv, k2.w, srow[11]);
                    srow[12] = fmaf(qv, k3.x, srow[12]); srow[13] = fmaf(qv, k3.y, srow[13]);
                    srow[14] = fmaf(qv, k3.z, srow[14]); srow[15] = fmaf(qv, k3.w, srow[15]);
                    srow[16] = fmaf(qv, k4.x, srow[16]); srow[17] = fmaf(qv, k4.y, srow[17]);
                }
                float mx = srow[0];
                #pragma unroll
                for (int j = 1; j < NJ; j++) mx = fmaxf(mx, srow[j]);
                float ssum = 0.f;
                #pragma unroll
                for (int j = 0; j < NJ; j++) { float e = __expf(srow[j] - mx); srow[j] = e; ssum += e; }
                float sc = sm->cw[i] / ssum;
                #pragma unroll
                for (int j = 0; j < NJ; j++) srow[j] *= sc;
            } else {
                #pragma unroll
                for (int j = 0; j < NJ; j++) srow[j] = 0.f;
            }
            // butterfly-reduce over il (lanes 0-15 / 16-31 are the two h halves)
            #pragma unroll
            for (int j = 0; j < NJ; j++) {
                float v = srow[j];
                v += __shfl_xor_sync(0xffffffffu, v, 1);
                v += __shfl_xor_sync(0xffffffffu, v, 2);
                v += __shfl_xor_sync(0xffffffffu, v, 4);
                v += __shfl_xor_sync(0xffffffffu, v, 8);
                Aj[j] += v;
            }
        }
        // no extra barrier: next a0-sync orders (c) reads before next a1 writes
    }
    if (tid < 256 && (tid & 15) == 0) {
        int h = tid >> 4;
        #pragma unroll
        for (int j = 0; j < NJ; j++) sm->Ash[h * NJ + j] = Aj[j];
    }
    __syncthreads();

    // ================= Tail: pooled attention output -> w_out -> residual -> LN =================
    if (tid < 256) {
        const int h = tid >> 4;
        const float* vr = sm->vsh + tid * KROW;
        const float* Ar = sm->Ash + h * NJ;
        float acc = 0.f;
        #pragma unroll
        for (int j = 0; j < NJ; j++) acc = fmaf(Ar[j], vr[j], acc);
        sm->pp[tid] = acc;
    }
    __syncthreads();
    {
        float y = 0.f;
        if (tid < 256) {
            float s0 = 0.f, s1 = 0.f, s2 = 0.f, s3 = 0.f;
            for (int t = 0; t < NSP; t += 4) {
                s0 += sm->cw[t]; s1 += sm->cw[t + 1]; s2 += sm->cw[t + 2]; s3 += sm->cw[t + 3];
            }
            float sumcw = (s0 + s1) + (s2 + s3);
            float acc = sumcw * __ldg(b_out + tid) + __ldg(conv1d_b);
            const float* wor = w_out + tid * ND;
            for (int c = 0; c < ND; c += 4) {
                float4 w4 = *(const float4*)(wor + c);
                acc = fmaf(w4.x, sm->pp[c],     acc);
                acc = fmaf(w4.y, sm->pp[c + 1], acc);
                acc = fmaf(w4.z, sm->pp[c + 2], acc);
                acc = fmaf(w4.w, sm->pp[c + 3], acc);
            }
            y = acc + sm->qsh[tid];
            float s = y, sq = y * y;
            #pragma unroll
            for (int o = 16; o > 0; o >>= 1) {
                s  += __shfl_xor_sync(0xffffffffu, s,  o);
                sq += __shfl_xor_sync(0xffffffffu, sq, o);
            }
            if (lane == 0) { sm->red[wid] = s; sm->red[8 + wid] = sq; }
        }
        __syncthreads();
        if (tid == 0) {
            float t1 = 0.f, t2 = 0.f;
            #pragma unroll
            for (int w8 = 0; w8 < 8; w8++) { t1 += sm->red[w8]; t2 += sm->red[8 + w8]; }
            float mu = t1 * (1.0f / 256.0f);
            sm->stats[0] = mu;
            sm->stats[1] = t2 * (1.0f / 256.0f) - mu * mu;
        }
        __syncthreads();
        if (tid < 256) {
            float mu = sm->stats[0], var = sm->stats[1];
            out[b * ND + tid] = (y - mu) * rsqrtf(var + 1e-5f) * __ldg(ln_g + tid) + __ldg(ln_b + tid);
        }
    }
}

extern "C" void kernel_launch(void* const* d_in, const int* in_sizes, int n_in,
                              void* d_out, int out_size)
{
    const float* x        = (const float*)d_in[0];
    const float* q        = (const float*)d_in[1];
    const float* w_off_dw = (const float*)d_in[2];
    const float* b_off_dw = (const float*)d_in[3];
    const float* w_off_pw = (const float*)d_in[4];
    const float* wk       = (const float*)d_in[5];
    const float* wv       = (const float*)d_in[6];
    const float* w_out    = (const float*)d_in[7];
    const float* b_out    = (const float*)d_in[8];
    const float* cpb_w1   = (const float*)d_in[9];
    const float* cpb_b1   = (const float*)d_in[10];
    const float* cpb_w2   = (const float*)d_in[11];
    const float* cpb_b2   = (const float*)d_in[12];
    const float* cpb_w3   = (const float*)d_in[13];
    const float* cpb_b3   = (const float*)d_in[14];
    const float* conv1d_w = (const float*)d_in[15];
    const float* conv1d_b = (const float*)d_in[16];
    const float* ln_g     = (const float*)d_in[17];
    const float* ln_b     = (const float*)d_in[18];
    float* out = (float*)d_out;

    (void)in_sizes; (void)n_in; (void)out_size;

    cudaFuncSetAttribute(sca_kernel, cudaFuncAttributeMaxDynamicSharedMemorySize, (int)sizeof(SM));
    sca_kernel<<<NB, NTHR, sizeof(SM)>>>(x, q, w_off_dw, b_off_dw, w_off_pw, wk, wv,
                                         w_out, b_out, cpb_w1, cpb_b1, cpb_w2, cpb_b2,
                                         cpb_w3, cpb_b3, conv1d_w, conv1d_b, ln_g, ln_b, out);
}